// round 3
// baseline (speedup 1.0000x reference)
#include <cuda_runtime.h>
#include <cuda_bf16.h>

// YoloLayer: x (16, 3*85, 76, 76) f32  ->  out (16, 3, 76, 76, 85) f32
// attr0: (gi + sigmoid)/76, attr1: (gj + sigmoid)/76,
// attr2: exp*aw/608, attr3: exp*ah/608, attr4..84: sigmoid
// (faithful to reference's anchor indexing: aw = {10,13,16}, ah = {13,16,30})

namespace {

constexpr int ATTRS   = 85;
constexpr int W       = 76;
constexpr int H       = 76;
constexpr int HW      = W * H;          // 5776
constexpr int PAD     = 77;             // gcd(77,32)=1 -> conflict-free scatter reads
constexpr int THREADS = 256;
constexpr int PER_BA  = ATTRS * HW;     // 491060 floats; same (b,a) stride in & out
constexpr int W4      = W / 4;          // 19 float4 per attr-row
constexpr int NLOAD4  = ATTRS * W4;     // 1615 float4 per CTA tile

__constant__ float c_aw[3] = {10.0f / 608.0f, 13.0f / 608.0f, 16.0f / 608.0f};
__constant__ float c_ah[3] = {13.0f / 608.0f, 16.0f / 608.0f, 30.0f / 608.0f};

__device__ __forceinline__ float sigmoidf(float v) {
    // EX2 + RCP via fast intrinsics; rel error ~1e-7, far under 1e-3 budget
    return __fdividef(1.0f, 1.0f + __expf(-v));
}

__global__ __launch_bounds__(THREADS) void yolo_kernel(
    const float* __restrict__ x, float* __restrict__ out) {
    __shared__ float sm[ATTRS * PAD];

    const int h  = blockIdx.x;      // image row  (gj = h)
    const int ba = blockIdx.y;      // b*3 + a
    const int a  = ba % 3;

    // ---- load phase: 85 attr-planes x 19 float4, fully coalesced LDG.128 ----
    // Alignment: plane stride 5776*4B % 16 == 0, row offset h*76*4B % 16 == 0.
    {
        const float4* in4 = reinterpret_cast<const float4*>(
            x + (size_t)ba * PER_BA + (size_t)h * W);
        constexpr int HW4 = HW / 4;                 // 1444 float4 per plane
        for (int i = threadIdx.x; i < NLOAD4; i += THREADS) {
            const int attr = i / W4;                // magic-number div by 19
            const int q    = i - attr * W4;
            float4 v = in4[attr * HW4 + q];
            float* dst = &sm[attr * PAD + 4 * q];
            dst[0] = v.x; dst[1] = v.y; dst[2] = v.z; dst[3] = v.w;
        }
    }
    __syncthreads();

    // ---- store phase: attr-contiguous output, fully coalesced STG.32 ----
    const float aw = c_aw[a];
    const float ah = c_ah[a];
    const float gj = (float)h;
    float* o = out + (size_t)ba * PER_BA + (size_t)h * (W * ATTRS);

    #pragma unroll 4
    for (int i = threadIdx.x; i < W * ATTRS; i += THREADS) {
        const int s    = i / ATTRS;               // spatial (gi = s); mul-hi div
        const int attr = i - s * ATTRS;
        const float v  = sm[attr * PAD + s];      // stride 77 words -> conflict-free

        float r;
        if (attr >= 5) {
            r = sigmoidf(v);                               // class probs
        } else if (attr == 0) {
            r = ((float)s + sigmoidf(v)) * (1.0f / 76.0f); // bx
        } else if (attr == 1) {
            r = (gj + sigmoidf(v)) * (1.0f / 76.0f);       // by
        } else if (attr == 2) {
            r = __expf(v) * aw;                            // bw
        } else if (attr == 3) {
            r = __expf(v) * ah;                            // bh
        } else { // attr == 4
            r = sigmoidf(v);                               // conf
        }
        o[i] = r;
    }
}

} // namespace

extern "C" void kernel_launch(void* const* d_in, const int* in_sizes, int n_in,
                              void* d_out, int out_size) {
    const float* x  = (const float*)d_in[0];
    float* out      = (float*)d_out;
    dim3 grid(H, 48);   // 76 rows x (16 batches * 3 anchors)
    yolo_kernel<<<grid, THREADS>>>(x, out);
}

// round 17
// speedup vs baseline: 1.1648x; 1.1648x over previous
#include <cuda_runtime.h>
#include <cuda_bf16.h>

// YoloLayer: x (16, 3*85, 76, 76) f32  ->  out (16, 3, 76, 76, 85) f32
// attr0: (gi + sig)/76, attr1: (gj + sig)/76, attr2: exp*aw/608,
// attr3: exp*ah/608, attr>=4: sigmoid
// (faithful to reference's anchor indexing: aw = {10,13,16}, ah = {13,16,30})

namespace {

constexpr int ATTRS   = 85;
constexpr int W       = 76;
constexpr int H       = 76;
constexpr int HW      = W * H;          // 5776
constexpr int THREADS = 256;
constexpr int PER_BA  = ATTRS * HW;     // 491060 floats; same (b,a) stride in & out
constexpr int TILE    = ATTRS * W;      // 6460 floats per CTA tile (25.84 KB)
constexpr float INV76 = 1.0f / 76.0f;

__constant__ float c_aw[3] = {10.0f / 608.0f, 13.0f / 608.0f, 16.0f / 608.0f};
__constant__ float c_ah[3] = {13.0f / 608.0f, 16.0f / 608.0f, 30.0f / 608.0f};

__global__ __launch_bounds__(THREADS) void yolo_kernel(
    const float* __restrict__ x, float* __restrict__ out) {
    // Transposed tile: sm[s*85 + attr] == exact output order for this row.
    __shared__ float sm[TILE];

    const int h  = blockIdx.x;      // image row (gj = h)
    const int ba = blockIdx.y;      // b*3 + a
    const int a  = ba % 3;

    // ---- load: coalesced LDG.32 (consecutive s), STS stride 85 (odd) ----
    const float* in = x + (size_t)ba * PER_BA + (size_t)h * W;
    #pragma unroll 4
    for (int i = threadIdx.x; i < TILE; i += THREADS) {
        const int attr = i / W;                 // mul-hi div by 76
        const int s    = i - attr * W;
        sm[s * ATTRS + attr] = in[attr * HW + s];
    }
    __syncthreads();

    // ---- store: LDS.128 + STG.128, branch-free predicated math ----
    const float aw  = c_aw[a];
    const float ah  = c_ah[a];
    const float gjo = (float)h * INV76;
    float4* o4 = reinterpret_cast<float4*>(
        out + (size_t)ba * PER_BA + (size_t)h * (W * ATTRS));
    const float4* sm4 = reinterpret_cast<const float4*>(sm);

    #pragma unroll 2
    for (int t = threadIdx.x; t < TILE / 4; t += THREADS) {   // 1615 float4
        const float4 v4 = sm4[t];                             // aligned, conflict-free
        const int f  = t * 4;
        const int s0 = f / ATTRS;                             // mul-hi div by 85
        const int a0 = f - s0 * ATTRS;
        const float vv[4] = {v4.x, v4.y, v4.z, v4.w};
        float r[4];

        #pragma unroll
        for (int j = 0; j < 4; j++) {
            int aj = a0 + j;
            int sj = s0;
            if (aj >= ATTRS) { aj -= ATTRS; sj++; }           // predicated fixup

            const float v     = vv[j];
            const bool  isExp = ((unsigned)(aj - 2)) < 2u;    // aj==2 || aj==3
            const float e     = __expf(isExp ? v : -v);       // FMUL + MUFU.EX2
            const float u     = isExp ? e : e + 1.0f;
            const float tt    = isExp ? u : __fdividef(1.0f, u); // MUFU.RCP
            const float scale = (aj >= 4) ? 1.0f
                              : (aj <  2) ? INV76
                              : (aj == 2) ? aw : ah;
            const float off   = (aj == 0) ? (float)sj * INV76
                              : (aj == 1) ? gjo : 0.0f;
            r[j] = fmaf(tt, scale, off);
        }
        o4[t] = make_float4(r[0], r[1], r[2], r[3]);
    }
}

} // namespace

extern "C" void kernel_launch(void* const* d_in, const int* in_sizes, int n_in,
                              void* d_out, int out_size) {
    const float* x  = (const float*)d_in[0];
    float* out      = (float*)d_out;
    dim3 grid(H, 48);   // 76 rows x (16 batches * 3 anchors)
    yolo_kernel<<<grid, THREADS>>>(x, out);
}